// round 15
// baseline (speedup 1.0000x reference)
#include <cuda_runtime.h>
#include <cuda_fp16.h>
#include <cstdint>

#define B_  4
#define T_  2048
#define DM  1024
#define H_  16
#define DH  64
#define E3  (3*DM)        // 3072
#define MTOT (B_*T_)      // 8192

// Scratch (allowed: __device__ globals)
__device__ __half g_qkvh[(size_t)MTOT * E3];  // [B*T, 3072] (q|k|v), fp16
__device__ __half g_yh  [(size_t)MTOT * DM];  // attention out, fp16
__device__ __half g_xh  [(size_t)MTOT * DM];  // x in fp16
__device__ __half g_wqh [(size_t)E3 * DM];    // w_qkv fp16
__device__ __half g_woh [(size_t)DM * DM];    // w_out fp16

// m16n8k16 fp16 MMA, fp32 accumulate
__device__ __forceinline__ void mma_f16(float* d, const uint32_t* a, const uint32_t* b) {
    asm volatile(
        "mma.sync.aligned.m16n8k16.row.col.f32.f16.f16.f32 "
        "{%0,%1,%2,%3}, {%4,%5,%6,%7}, {%8,%9}, {%0,%1,%2,%3};"
        : "+f"(d[0]), "+f"(d[1]), "+f"(d[2]), "+f"(d[3])
        : "r"(a[0]), "r"(a[1]), "r"(a[2]), "r"(a[3]),
          "r"(b[0]), "r"(b[1]));
}

__device__ __forceinline__ uint32_t smem_u32(const void* p) {
    uint32_t a;
    asm("{ .reg .u64 t; cvta.to.shared.u64 t, %1; cvt.u32.u64 %0, t; }"
        : "=r"(a) : "l"(p));
    return a;
}
__device__ __forceinline__ void cp16(uint32_t dst, const void* src) {
    asm volatile("cp.async.cg.shared.global [%0], [%1], 16;" :: "r"(dst), "l"(src));
}
#define CP_COMMIT() asm volatile("cp.async.commit_group;" ::: "memory")
#define CP_WAIT0()  asm volatile("cp.async.wait_group 0;" ::: "memory")
#define CP_WAIT1()  asm volatile("cp.async.wait_group 1;" ::: "memory")

#define LDSM_X4(r0, r1, r2, r3, addr) \
    asm volatile("ldmatrix.sync.aligned.m8n8.x4.shared.b16 {%0,%1,%2,%3}, [%4];" \
                 : "=r"(r0), "=r"(r1), "=r"(r2), "=r"(r3) : "r"(addr))
#define LDSM_X4_T(r0, r1, r2, r3, addr) \
    asm volatile("ldmatrix.sync.aligned.m8n8.x4.trans.shared.b16 {%0,%1,%2,%3}, [%4];" \
                 : "=r"(r0), "=r"(r1), "=r"(r2), "=r"(r3) : "r"(addr))

__device__ __forceinline__ uint32_t h2pack(float a, float b) {
    __half2 h = __floats2half2_rn(a, b);
    return *(uint32_t*)&h;
}
// packed half2 exp2
__device__ __forceinline__ uint32_t ex2h2(uint32_t x) {
    uint32_t r;
    asm("ex2.approx.f16x2 %0, %1;" : "=r"(r) : "r"(x));
    return r;
}

// ============================================================================
// Fused fp32 -> fp16 rounding of all three inputs in one launch.
// ============================================================================
#define N4X (MTOT * DM / 4)
#define N4Q (E3 * DM / 4)
#define N4O (DM * DM / 4)

__global__ void round_all(const float* __restrict__ x,
                          const float* __restrict__ wq,
                          const float* __restrict__ wo,
                          __half* __restrict__ xh,
                          __half* __restrict__ wqh,
                          __half* __restrict__ woh) {
    int i = blockIdx.x * blockDim.x + threadIdx.x;
    const float* src;
    __half* dst;
    if (i < N4X)                 { src = x;  dst = xh; }
    else if (i < N4X + N4Q)      { src = wq; dst = wqh; i -= N4X; }
    else if (i < N4X + N4Q + N4O){ src = wo; dst = woh; i -= (N4X + N4Q); }
    else return;
    float4 v = ((const float4*)src)[i];
    *(__half2*)(dst + 4 * (size_t)i)     = __floats2half2_rn(v.x, v.y);
    *(__half2*)(dst + 4 * (size_t)i + 2) = __floats2half2_rn(v.z, v.w);
}

// ============================================================================
// FP16 tensor-core NT GEMM — R11 proven inner loop (2-stage, two barriers),
// persistent with CROSS-TILE PREFETCH: next tile's stage-0 cp.async is issued
// during the last k-iteration, eliminating the tile-boundary latency bubble.
// C[M,N] = A[M,K] * Bw[N,K]^T, CTA tile 128x128, K-tile 64, 256 thr, 2 CTA/SM.
// ============================================================================
#define HST 72
#define TILE_H (128 * HST)
#define STAGE_H (2 * TILE_H)
#define GEMM_SMEM (2 * STAGE_H * 2)    // 73728 B
#define NSM_CTAS 296                   // 148 SMs x 2 CTA/SM

__global__ __launch_bounds__(256, 2) void gemm_h(const __half* __restrict__ A,
                                                 const __half* __restrict__ Bw,
                                                 void* __restrict__ Cv,
                                                 int N, int K, int half_out,
                                                 int ntiles, int ncols) {
    extern __shared__ __half smh[];
    const uint32_t smb = smem_u32(smh);

    const int tid  = threadIdx.x;
    const int lane = tid & 31;
    const int wid  = tid >> 5;
    const int wm   = wid & 1;
    const int wn   = wid >> 1;
    const int g    = lane >> 2;
    const int tig  = lane & 3;

    const int a_m = (lane & 7) + ((lane >> 3) & 1) * 8;
    const int a_k = (lane >> 4) * 8;
    const uint32_t a_off = (uint32_t)(((wm * 64 + a_m) * HST + a_k) * 2);
    const int b_n = (lane & 7) + (lane >> 4) * 8;
    const int b_k = ((lane >> 3) & 1) * 8;
    const uint32_t b_off = (uint32_t)(((wn * 32 + b_n) * HST + b_k) * 2);

    const int NKT = K / 64;

    // stage loader with explicit tile base pointers (for cross-tile prefetch)
    auto cpa = [&](int s, int kt, const __half* Ag, const __half* Bg) {
        const int k0 = kt * 64;
        #pragma unroll
        for (int i = 0; i < 4; i++) {
            const int idx = i * 256 + tid;
            const int row = idx >> 3;
            const int c8  = (idx & 7) * 8;
            cp16(smb + (uint32_t)((s * STAGE_H + row * HST + c8) * 2),
                 Ag + (size_t)row * K + k0 + c8);
            cp16(smb + (uint32_t)((s * STAGE_H + TILE_H + row * HST + c8) * 2),
                 Bg + (size_t)row * K + k0 + c8);
        }
    };
    auto tileA = [&](int t) { return A  + (size_t)((t / ncols) * 128) * K; };
    auto tileB = [&](int t) { return Bw + (size_t)((t % ncols) * 128) * K; };

    int tile = blockIdx.x;
    if (tile < ntiles) {            // initial stage-0 prefetch
        cpa(0, 0, tileA(tile), tileB(tile));
        CP_COMMIT();
    }

    for (; tile < ntiles; tile += gridDim.x) {
        const int bm = (tile / ncols) * 128;
        const int bn = (tile % ncols) * 128;
        const __half* Ag = A  + (size_t)bm * K;
        const __half* Bg = Bw + (size_t)bn * K;
        const int ntile = tile + gridDim.x;

        float acc[4][4][4];
        #pragma unroll
        for (int mt = 0; mt < 4; mt++)
            #pragma unroll
            for (int nt = 0; nt < 4; nt++)
                #pragma unroll
                for (int q = 0; q < 4; q++) acc[mt][nt][q] = 0.f;

        for (int kt = 0; kt < NKT; kt++) {
            const int cur = kt & 1;
            if (kt + 1 < NKT) { cpa(cur ^ 1, kt + 1, Ag, Bg); CP_COMMIT(); CP_WAIT1(); }
            else              { CP_WAIT0(); }
            __syncthreads();

            // cross-tile prefetch: stage 0 is free (last read kt=NKT-2, proven
            // by the barrier above); overlaps next tile's loads with the final
            // MMA section + epilogue of this tile.
            if (kt == NKT - 1 && ntile < ntiles) {
                cpa(0, 0, tileA(ntile), tileB(ntile));
                CP_COMMIT();
            }

            const uint32_t aB = smb + (uint32_t)(cur * STAGE_H * 2) + a_off;
            const uint32_t bB = smb + (uint32_t)((cur * STAGE_H + TILE_H) * 2) + b_off;

            #pragma unroll
            for (int ks = 0; ks < 4; ks++) {
                uint32_t af[4][4], bf[4][2];
                #pragma unroll
                for (int mt = 0; mt < 4; mt++)
                    LDSM_X4(af[mt][0], af[mt][1], af[mt][2], af[mt][3],
                            aB + (uint32_t)((mt * 16 * HST + ks * 16) * 2));
                #pragma unroll
                for (int ntp = 0; ntp < 2; ntp++) {
                    uint32_t r0, r1, r2, r3;
                    LDSM_X4(r0, r1, r2, r3,
                            bB + (uint32_t)((ntp * 16 * HST + ks * 16) * 2));
                    bf[2 * ntp][0] = r0; bf[2 * ntp][1] = r1;
                    bf[2 * ntp + 1][0] = r2; bf[2 * ntp + 1][1] = r3;
                }
                #pragma unroll
                for (int mt = 0; mt < 4; mt++)
                    #pragma unroll
                    for (int nt = 0; nt < 4; nt++)
                        mma_f16(acc[mt][nt], af[mt], bf[nt]);
            }
            __syncthreads();   // all warps done reading both stages
        }

        #pragma unroll
        for (int mt = 0; mt < 4; mt++) {
            const int r = bm + wm * 64 + mt * 16 + g;
            #pragma unroll
            for (int nt = 0; nt < 4; nt++) {
                const int c = bn + wn * 32 + nt * 8 + 2 * tig;
                if (half_out) {
                    __half* Ch = (__half*)Cv;
                    *(__half2*)(Ch + (size_t)r * N + c) =
                        __floats2half2_rn(acc[mt][nt][0], acc[mt][nt][1]);
                    *(__half2*)(Ch + (size_t)(r + 8) * N + c) =
                        __floats2half2_rn(acc[mt][nt][2], acc[mt][nt][3]);
                } else {
                    float* Cf = (float*)Cv;
                    *(float2*)(Cf + (size_t)r * N + c) =
                        make_float2(acc[mt][nt][0], acc[mt][nt][1]);
                    *(float2*)(Cf + (size_t)(r + 8) * N + c) =
                        make_float2(acc[mt][nt][2], acc[mt][nt][3]);
                }
            }
        }
    }
}

// ============================================================================
// FP16 flash attention — EXACT R11 structure (max-free softmax).
// ============================================================================
#define A_OFF_K (128 * HST)
#define A_KSTG  (64 * HST)
#define A_OFF_V (A_OFF_K + 2 * A_KSTG)
#define A_VSTG  (64 * HST)
#define ATT_SMEM ((A_OFF_V + 2 * A_VSTG) * 2)   // 55296 B

__global__ __launch_bounds__(256, 2) void attn_h() {
    extern __shared__ __half smh[];
    const uint32_t smb = smem_u32(smh);

    const int tid  = threadIdx.x;
    const int lane = tid & 31;
    const int w    = tid >> 5;
    const int g    = lane >> 2;
    const int tig  = lane & 3;

    const int bq = (gridDim.x - 1) - blockIdx.x;   // big tiles first
    const int h  = blockIdx.y;
    const int b  = blockIdx.z;
    const int qbase = bq * 128;
    const int nkt = 2 * bq + 2;

    const __half* kvbase = g_qkvh + (size_t)b * T_ * E3 + DM + h * DH;

    auto cpkv = [&](int kt, int s) {
        const __half* kg = kvbase + (size_t)(kt * 64) * E3;
        #pragma unroll
        for (int i = 0; i < 2; i++) {
            int idx = i * 256 + tid;
            int row = idx >> 3;
            int c8  = (idx & 7) * 8;
            cp16(smb + (uint32_t)((A_OFF_K + s * A_KSTG + row * HST + c8) * 2),
                 kg + (size_t)row * E3 + c8);
            cp16(smb + (uint32_t)((A_OFF_V + s * A_VSTG + row * HST + c8) * 2),
                 kg + DM + (size_t)row * E3 + c8);
        }
    };

    // ---- prologue: Q + K/V tile 0 via cp.async ----
    {
        const __half* qg = g_qkvh + ((size_t)b * T_ + qbase) * E3 + h * DH;
        #pragma unroll
        for (int i = 0; i < 4; i++) {
            int idx = i * 256 + tid;
            int row = idx >> 3;
            int c8  = (idx & 7) * 8;
            cp16(smb + (uint32_t)((row * HST + c8) * 2),
                 qg + (size_t)row * E3 + c8);
        }
    }
    cpkv(0, 0);
    CP_COMMIT();
    CP_WAIT0();
    __syncthreads();

    // hoist Q fragments, folding softmax scale (x2^-3, exact in fp16)
    uint32_t qf[4][4];
    {
        const __half2 sc = __floats2half2_rn(0.125f, 0.125f);
        const __half* qp = smh + (w * 16 + g) * HST + 2 * tig;
        #pragma unroll
        for (int ks = 0; ks < 4; ks++) {
            const __half* p = qp + 16 * ks;
            __half2 v0 = __hmul2(*(const __half2*)(p), sc);
            __half2 v1 = __hmul2(*(const __half2*)(p + 8 * HST), sc);
            __half2 v2 = __hmul2(*(const __half2*)(p + 8), sc);
            __half2 v3 = __hmul2(*(const __half2*)(p + 8 * HST + 8), sc);
            qf[ks][0] = *(uint32_t*)&v0;
            qf[ks][1] = *(uint32_t*)&v1;
            qf[ks][2] = *(uint32_t*)&v2;
            qf[ks][3] = *(uint32_t*)&v3;
        }
    }

    const int b_n = (lane & 7) + (lane >> 4) * 8;
    const int b_k = ((lane >> 3) & 1) * 8;
    const int lm_key = lane & 15;
    const int lm_d8  = (lane >> 4) << 3;

    float accO[8][4];
    #pragma unroll
    for (int nt = 0; nt < 8; nt++)
        #pragma unroll
        for (int q = 0; q < 4; q++) accO[nt][q] = 0.f;
    float accL[4] = { 0.f, 0.f, 0.f, 0.f };     // row sums via ones-MMA
    const uint32_t ones2[2] = { 0x3C003C00u, 0x3C003C00u };
    const float LOG2E = 1.4426950408889634f;

    const int r0 = qbase + w * 16 + g;
    const int r1 = r0 + 8;

    for (int kt = 0; kt < nkt; kt++) {
        const int s = kt & 1;
        if (kt > 0) { CP_WAIT0(); __syncthreads(); }
        if (kt + 1 < nkt) { cpkv(kt + 1, s ^ 1); CP_COMMIT(); }

        // ---- S = Q K^T ----
        float accS[8][4];
        #pragma unroll
        for (int nt = 0; nt < 8; nt++)
            #pragma unroll
            for (int q = 0; q < 4; q++) accS[nt][q] = 0.f;

        const uint32_t kB = smb + (uint32_t)((A_OFF_K + s * A_KSTG) * 2)
                          + (uint32_t)((b_n * HST + b_k) * 2);
        #pragma unroll
        for (int ks = 0; ks < 4; ks++) {
            #pragma unroll
            for (int ntp = 0; ntp < 4; ntp++) {
                uint32_t t0, t1, t2, t3;
                LDSM_X4(t0, t1, t2, t3,
                        kB + (uint32_t)((ntp * 16 * HST + ks * 16) * 2));
                uint32_t b01[2] = { t0, t1 };
                uint32_t b23[2] = { t2, t3 };
                mma_f16(accS[2 * ntp],     qf[ks], b01);
                mma_f16(accS[2 * ntp + 1], qf[ks], b23);
            }
        }

        // ---- causal mask (masked -> -1e30 -> fp16 -inf -> ex2 -> 0) ----
        if (kt >= nkt - 2) {
            #pragma unroll
            for (int nt = 0; nt < 8; nt++) {
                const int c0 = kt * 64 + 8 * nt + 2 * tig;
                if (c0     > r0) accS[nt][0] = -1e30f;
                if (c0 + 1 > r0) accS[nt][1] = -1e30f;
                if (c0     > r1) accS[nt][2] = -1e30f;
                if (c0 + 1 > r1) accS[nt][3] = -1e30f;
            }
        }

        // ---- P = exp2(S * log2e) straight into fp16 a-frags (no max) ----
        uint32_t pf[4][4];
        #pragma unroll
        for (int nt = 0; nt < 8; nt++) {
            uint32_t e01 = ex2h2(h2pack(accS[nt][0] * LOG2E, accS[nt][1] * LOG2E));
            uint32_t e23 = ex2h2(h2pack(accS[nt][2] * LOG2E, accS[nt][3] * LOG2E));
            pf[nt >> 1][(nt & 1) * 2 + 0] = e01;
            pf[nt >> 1][(nt & 1) * 2 + 1] = e23;
        }

        // ---- row sums via ones-MMA ----
        #pragma unroll
        for (int ks = 0; ks < 4; ks++)
            mma_f16(accL, pf[ks], ones2);

        // ---- O += P V ----
        const uint32_t vbase = smb + (uint32_t)((A_OFF_V + s * A_VSTG) * 2);
        #pragma unroll
        for (int ks = 0; ks < 4; ks++) {
            const uint32_t rowaddr = vbase + (uint32_t)(((16 * ks + lm_key) * HST) * 2);
            #pragma unroll
            for (int pdp = 0; pdp < 4; pdp++) {
                uint32_t t0, t1, t2, t3;
                LDSM_X4_T(t0, t1, t2, t3,
                          rowaddr + (uint32_t)((16 * pdp + lm_d8) * 2));
                uint32_t b01[2] = { t0, t1 };
                uint32_t b23[2] = { t2, t3 };
                mma_f16(accO[2 * pdp],     pf[ks], b01);
                mma_f16(accO[2 * pdp + 1], pf[ks], b23);
            }
        }
    }

    // ---- epilogue: normalize by exact fp32 row sums, store y (fp16) ----
    const float inv0 = 1.f / accL[0], inv1 = 1.f / accL[2];
    __half* yp = g_yh + ((size_t)b * T_ + qbase + w * 16) * DM + h * DH;
    #pragma unroll
    for (int nt = 0; nt < 8; nt++) {
        const int c = 8 * nt + 2 * tig;
        *(__half2*)(yp + (size_t)g * DM + c) =
            __floats2half2_rn(accO[nt][0] * inv0, accO[nt][1] * inv0);
        *(__half2*)(yp + (size_t)(g + 8) * DM + c) =
            __floats2half2_rn(accO[nt][2] * inv1, accO[nt][3] * inv1);
    }
}

// ---------------------------------------------------------------------------
extern "C" void kernel_launch(void* const* d_in, const int* in_sizes, int n_in,
                              void* d_out, int out_size) {
    const float* x     = (const float*)d_in[0];   // [B,T,1024]
    const float* w_qkv = (const float*)d_in[1];   // [3072,1024]
    const float* w_out = (const float*)d_in[2];   // [1024,1024]
    float* out = (float*)d_out;                   // [B,T,1024]

    __half *qkv_p, *y_p, *xh_p, *wqh_p, *woh_p;
    cudaGetSymbolAddress((void**)&qkv_p, g_qkvh);
    cudaGetSymbolAddress((void**)&y_p,   g_yh);
    cudaGetSymbolAddress((void**)&xh_p,  g_xh);
    cudaGetSymbolAddress((void**)&wqh_p, g_wqh);
    cudaGetSymbolAddress((void**)&woh_p, g_woh);

    cudaFuncSetAttribute(gemm_h, cudaFuncAttributeMaxDynamicSharedMemorySize,
                         GEMM_SMEM);
    cudaFuncSetAttribute(attn_h, cudaFuncAttributeMaxDynamicSharedMemorySize,
                         ATT_SMEM);

    // 0) round all inputs to fp16 (single launch)
    {
        int n4 = N4X + N4Q + N4O;
        round_all<<<(n4 + 255) / 256, 256>>>(x, w_qkv, w_out, xh_p, wqh_p, woh_p);
    }

    // 1) qkv = x @ w_qkv^T  (fp16 in, fp16 out) — persistent w/ prefetch
    {
        int ntiles = (MTOT / 128) * (E3 / 128);   // 1536
        gemm_h<<<NSM_CTAS, 256, GEMM_SMEM>>>(xh_p, wqh_p, qkv_p, E3, DM, 1,
                                             ntiles, E3 / 128);
    }

    // 2) flash attention (fp16 tensor core, max-free softmax) -> g_yh
    {
        dim3 grid(T_ / 128, H_, B_);
        attn_h<<<grid, 256, ATT_SMEM>>>();
    }

    // 3) out = y @ w_out^T  (fp16 in, fp32 out) — persistent w/ prefetch
    {
        int ntiles = (MTOT / 128) * (DM / 128);   // 512
        gemm_h<<<NSM_CTAS, 256, GEMM_SMEM>>>(y_p, woh_p, out, DM, DM, 0,
                                             ntiles, DM / 128);
    }
}

// round 16
// speedup vs baseline: 1.0537x; 1.0537x over previous
#include <cuda_runtime.h>
#include <cuda_fp16.h>
#include <cstdint>

#define B_  4
#define T_  2048
#define DM  1024
#define H_  16
#define DH  64
#define E3  (3*DM)        // 3072
#define MTOT (B_*T_)      // 8192

// Scratch (allowed: __device__ globals)
__device__ __half g_qkvh[(size_t)MTOT * E3];  // [B*T, 3072] (q|k|v), fp16
__device__ __half g_yh  [(size_t)MTOT * DM];  // attention out, fp16
__device__ __half g_xh  [(size_t)MTOT * DM];  // x in fp16
__device__ __half g_wqh [(size_t)E3 * DM];    // w_qkv fp16
__device__ __half g_woh [(size_t)DM * DM];    // w_out fp16

// m16n8k16 fp16 MMA, fp32 accumulate
__device__ __forceinline__ void mma_f16(float* d, const uint32_t* a, const uint32_t* b) {
    asm volatile(
        "mma.sync.aligned.m16n8k16.row.col.f32.f16.f16.f32 "
        "{%0,%1,%2,%3}, {%4,%5,%6,%7}, {%8,%9}, {%0,%1,%2,%3};"
        : "+f"(d[0]), "+f"(d[1]), "+f"(d[2]), "+f"(d[3])
        : "r"(a[0]), "r"(a[1]), "r"(a[2]), "r"(a[3]),
          "r"(b[0]), "r"(b[1]));
}

__device__ __forceinline__ uint32_t smem_u32(const void* p) {
    uint32_t a;
    asm("{ .reg .u64 t; cvta.to.shared.u64 t, %1; cvt.u32.u64 %0, t; }"
        : "=r"(a) : "l"(p));
    return a;
}
__device__ __forceinline__ void cp16(uint32_t dst, const void* src) {
    asm volatile("cp.async.cg.shared.global [%0], [%1], 16;" :: "r"(dst), "l"(src));
}
#define CP_COMMIT() asm volatile("cp.async.commit_group;" ::: "memory")
#define CP_WAIT0()  asm volatile("cp.async.wait_group 0;" ::: "memory")
#define CP_WAIT1()  asm volatile("cp.async.wait_group 1;" ::: "memory")

#define LDSM_X4(r0, r1, r2, r3, addr) \
    asm volatile("ldmatrix.sync.aligned.m8n8.x4.shared.b16 {%0,%1,%2,%3}, [%4];" \
                 : "=r"(r0), "=r"(r1), "=r"(r2), "=r"(r3) : "r"(addr))
#define LDSM_X4_T(r0, r1, r2, r3, addr) \
    asm volatile("ldmatrix.sync.aligned.m8n8.x4.trans.shared.b16 {%0,%1,%2,%3}, [%4];" \
                 : "=r"(r0), "=r"(r1), "=r"(r2), "=r"(r3) : "r"(addr))

__device__ __forceinline__ uint32_t h2pack(float a, float b) {
    __half2 h = __floats2half2_rn(a, b);
    return *(uint32_t*)&h;
}
// packed half2 exp2
__device__ __forceinline__ uint32_t ex2h2(uint32_t x) {
    uint32_t r;
    asm("ex2.approx.f16x2 %0, %1;" : "=r"(r) : "r"(x));
    return r;
}

// ============================================================================
// Fused fp32 -> fp16 rounding of all three inputs in one launch.
// ============================================================================
#define N4X (MTOT * DM / 4)
#define N4Q (E3 * DM / 4)
#define N4O (DM * DM / 4)

__global__ void round_all(const float* __restrict__ x,
                          const float* __restrict__ wq,
                          const float* __restrict__ wo,
                          __half* __restrict__ xh,
                          __half* __restrict__ wqh,
                          __half* __restrict__ woh) {
    int i = blockIdx.x * blockDim.x + threadIdx.x;
    const float* src;
    __half* dst;
    if (i < N4X)                 { src = x;  dst = xh; }
    else if (i < N4X + N4Q)      { src = wq; dst = wqh; i -= N4X; }
    else if (i < N4X + N4Q + N4O){ src = wo; dst = woh; i -= (N4X + N4Q); }
    else return;
    float4 v = ((const float4*)src)[i];
    *(__half2*)(dst + 4 * (size_t)i)     = __floats2half2_rn(v.x, v.y);
    *(__half2*)(dst + 4 * (size_t)i + 2) = __floats2half2_rn(v.z, v.w);
}

// ============================================================================
// FP16 tensor-core NT GEMM, ldmatrix fragments — EXACT R11 champion structure.
// C[M,N] = A[M,K] * Bw[N,K]^T, CTA 128x128, K-tile 64, 2-stage, 2 CTA/SM.
// ============================================================================
#define HST 72
#define TILE_H (128 * HST)
#define STAGE_H (2 * TILE_H)
#define GEMM_SMEM (2 * STAGE_H * 2)    // 73728 B

__global__ __launch_bounds__(256, 2) void gemm_h(const __half* __restrict__ A,
                                                 const __half* __restrict__ Bw,
                                                 void* __restrict__ Cv,
                                                 int N, int K, int half_out) {
    extern __shared__ __half smh[];
    const uint32_t smb = smem_u32(smh);

    const int tid  = threadIdx.x;
    const int lane = tid & 31;
    const int wid  = tid >> 5;
    const int wm   = wid & 1;
    const int wn   = wid >> 1;
    const int g    = lane >> 2;
    const int tig  = lane & 3;

    const int bm = blockIdx.y * 128;
    const int bn = blockIdx.x * 128;
    const __half* Ag = A  + (size_t)bm * K;
    const __half* Bg = Bw + (size_t)bn * K;

    const int a_m = (lane & 7) + ((lane >> 3) & 1) * 8;
    const int a_k = (lane >> 4) * 8;
    const uint32_t a_off = (uint32_t)(((wm * 64 + a_m) * HST + a_k) * 2);
    const int b_n = (lane & 7) + (lane >> 4) * 8;
    const int b_k = ((lane >> 3) & 1) * 8;
    const uint32_t b_off = (uint32_t)(((wn * 32 + b_n) * HST + b_k) * 2);

    float acc[4][4][4];
    #pragma unroll
    for (int mt = 0; mt < 4; mt++)
        #pragma unroll
        for (int nt = 0; nt < 4; nt++)
            #pragma unroll
            for (int q = 0; q < 4; q++) acc[mt][nt][q] = 0.f;

    auto cpa = [&](int s, int kt) {
        const int k0 = kt * 64;
        #pragma unroll
        for (int i = 0; i < 4; i++) {
            const int idx = i * 256 + tid;
            const int row = idx >> 3;
            const int c8  = (idx & 7) * 8;
            cp16(smb + (uint32_t)((s * STAGE_H + row * HST + c8) * 2),
                 Ag + (size_t)row * K + k0 + c8);
            cp16(smb + (uint32_t)((s * STAGE_H + TILE_H + row * HST + c8) * 2),
                 Bg + (size_t)row * K + k0 + c8);
        }
    };

    const int NKT = K / 64;
    cpa(0, 0);
    CP_COMMIT();

    for (int kt = 0; kt < NKT; kt++) {
        const int cur = kt & 1;
        if (kt + 1 < NKT) { cpa(cur ^ 1, kt + 1); CP_COMMIT(); CP_WAIT1(); }
        else              { CP_WAIT0(); }
        __syncthreads();

        const uint32_t aB = smb + (uint32_t)(cur * STAGE_H * 2) + a_off;
        const uint32_t bB = smb + (uint32_t)((cur * STAGE_H + TILE_H) * 2) + b_off;

        #pragma unroll
        for (int ks = 0; ks < 4; ks++) {
            uint32_t af[4][4], bf[4][2];
            #pragma unroll
            for (int mt = 0; mt < 4; mt++)
                LDSM_X4(af[mt][0], af[mt][1], af[mt][2], af[mt][3],
                        aB + (uint32_t)((mt * 16 * HST + ks * 16) * 2));
            #pragma unroll
            for (int ntp = 0; ntp < 2; ntp++) {
                uint32_t r0, r1, r2, r3;
                LDSM_X4(r0, r1, r2, r3,
                        bB + (uint32_t)((ntp * 16 * HST + ks * 16) * 2));
                bf[2 * ntp][0] = r0; bf[2 * ntp][1] = r1;
                bf[2 * ntp + 1][0] = r2; bf[2 * ntp + 1][1] = r3;
            }
            #pragma unroll
            for (int mt = 0; mt < 4; mt++)
                #pragma unroll
                for (int nt = 0; nt < 4; nt++)
                    mma_f16(acc[mt][nt], af[mt], bf[nt]);
        }
        __syncthreads();
    }

    #pragma unroll
    for (int mt = 0; mt < 4; mt++) {
        const int r = bm + wm * 64 + mt * 16 + g;
        #pragma unroll
        for (int nt = 0; nt < 4; nt++) {
            const int c = bn + wn * 32 + nt * 8 + 2 * tig;
            if (half_out) {
                __half* Ch = (__half*)Cv;
                *(__half2*)(Ch + (size_t)r * N + c) =
                    __floats2half2_rn(acc[mt][nt][0], acc[mt][nt][1]);
                *(__half2*)(Ch + (size_t)(r + 8) * N + c) =
                    __floats2half2_rn(acc[mt][nt][2], acc[mt][nt][3]);
            } else {
                float* Cf = (float*)Cv;
                *(float2*)(Cf + (size_t)r * N + c) =
                    make_float2(acc[mt][nt][0], acc[mt][nt][1]);
                *(float2*)(Cf + (size_t)(r + 8) * N + c) =
                    make_float2(acc[mt][nt][2], acc[mt][nt][3]);
            }
        }
    }
}

// ============================================================================
// FP16 flash attention — EXACT R11 champion (max-free softmax, ones-MMA sums).
// ============================================================================
#define A_OFF_K (128 * HST)
#define A_KSTG  (64 * HST)
#define A_OFF_V (A_OFF_K + 2 * A_KSTG)
#define A_VSTG  (64 * HST)
#define ATT_SMEM ((A_OFF_V + 2 * A_VSTG) * 2)   // 55296 B

__global__ __launch_bounds__(256, 2) void attn_h() {
    extern __shared__ __half smh[];
    const uint32_t smb = smem_u32(smh);

    const int tid  = threadIdx.x;
    const int lane = tid & 31;
    const int w    = tid >> 5;
    const int g    = lane >> 2;
    const int tig  = lane & 3;

    const int bq = (gridDim.x - 1) - blockIdx.x;   // big tiles first
    const int h  = blockIdx.y;
    const int b  = blockIdx.z;
    const int qbase = bq * 128;
    const int nkt = 2 * bq + 2;

    const __half* kvbase = g_qkvh + (size_t)b * T_ * E3 + DM + h * DH;

    auto cpkv = [&](int kt, int s) {
        const __half* kg = kvbase + (size_t)(kt * 64) * E3;
        #pragma unroll
        for (int i = 0; i < 2; i++) {
            int idx = i * 256 + tid;
            int row = idx >> 3;
            int c8  = (idx & 7) * 8;
            cp16(smb + (uint32_t)((A_OFF_K + s * A_KSTG + row * HST + c8) * 2),
                 kg + (size_t)row * E3 + c8);
            cp16(smb + (uint32_t)((A_OFF_V + s * A_VSTG + row * HST + c8) * 2),
                 kg + DM + (size_t)row * E3 + c8);
        }
    };

    // ---- prologue: Q + K/V tile 0 via cp.async ----
    {
        const __half* qg = g_qkvh + ((size_t)b * T_ + qbase) * E3 + h * DH;
        #pragma unroll
        for (int i = 0; i < 4; i++) {
            int idx = i * 256 + tid;
            int row = idx >> 3;
            int c8  = (idx & 7) * 8;
            cp16(smb + (uint32_t)((row * HST + c8) * 2),
                 qg + (size_t)row * E3 + c8);
        }
    }
    cpkv(0, 0);
    CP_COMMIT();
    CP_WAIT0();
    __syncthreads();

    // hoist Q fragments, folding softmax scale (x2^-3, exact in fp16)
    uint32_t qf[4][4];
    {
        const __half2 sc = __floats2half2_rn(0.125f, 0.125f);
        const __half* qp = smh + (w * 16 + g) * HST + 2 * tig;
        #pragma unroll
        for (int ks = 0; ks < 4; ks++) {
            const __half* p = qp + 16 * ks;
            __half2 v0 = __hmul2(*(const __half2*)(p), sc);
            __half2 v1 = __hmul2(*(const __half2*)(p + 8 * HST), sc);
            __half2 v2 = __hmul2(*(const __half2*)(p + 8), sc);
            __half2 v3 = __hmul2(*(const __half2*)(p + 8 * HST + 8), sc);
            qf[ks][0] = *(uint32_t*)&v0;
            qf[ks][1] = *(uint32_t*)&v1;
            qf[ks][2] = *(uint32_t*)&v2;
            qf[ks][3] = *(uint32_t*)&v3;
        }
    }

    const int b_n = (lane & 7) + (lane >> 4) * 8;
    const int b_k = ((lane >> 3) & 1) * 8;
    const int lm_key = lane & 15;
    const int lm_d8  = (lane >> 4) << 3;

    float accO[8][4];
    #pragma unroll
    for (int nt = 0; nt < 8; nt++)
        #pragma unroll
        for (int q = 0; q < 4; q++) accO[nt][q] = 0.f;
    float accL[4] = { 0.f, 0.f, 0.f, 0.f };     // row sums via ones-MMA
    const uint32_t ones2[2] = { 0x3C003C00u, 0x3C003C00u };
    const float LOG2E = 1.4426950408889634f;

    const int r0 = qbase + w * 16 + g;
    const int r1 = r0 + 8;

    for (int kt = 0; kt < nkt; kt++) {
        const int s = kt & 1;
        if (kt > 0) { CP_WAIT0(); __syncthreads(); }
        if (kt + 1 < nkt) { cpkv(kt + 1, s ^ 1); CP_COMMIT(); }

        // ---- S = Q K^T ----
        float accS[8][4];
        #pragma unroll
        for (int nt = 0; nt < 8; nt++)
            #pragma unroll
            for (int q = 0; q < 4; q++) accS[nt][q] = 0.f;

        const uint32_t kB = smb + (uint32_t)((A_OFF_K + s * A_KSTG) * 2)
                          + (uint32_t)((b_n * HST + b_k) * 2);
        #pragma unroll
        for (int ks = 0; ks < 4; ks++) {
            #pragma unroll
            for (int ntp = 0; ntp < 4; ntp++) {
                uint32_t t0, t1, t2, t3;
                LDSM_X4(t0, t1, t2, t3,
                        kB + (uint32_t)((ntp * 16 * HST + ks * 16) * 2));
                uint32_t b01[2] = { t0, t1 };
                uint32_t b23[2] = { t2, t3 };
                mma_f16(accS[2 * ntp],     qf[ks], b01);
                mma_f16(accS[2 * ntp + 1], qf[ks], b23);
            }
        }

        // ---- causal mask (masked -> -1e30 -> fp16 -inf -> ex2 -> 0) ----
        if (kt >= nkt - 2) {
            #pragma unroll
            for (int nt = 0; nt < 8; nt++) {
                const int c0 = kt * 64 + 8 * nt + 2 * tig;
                if (c0     > r0) accS[nt][0] = -1e30f;
                if (c0 + 1 > r0) accS[nt][1] = -1e30f;
                if (c0     > r1) accS[nt][2] = -1e30f;
                if (c0 + 1 > r1) accS[nt][3] = -1e30f;
            }
        }

        // ---- P = exp2(S * log2e) straight into fp16 a-frags (no max) ----
        uint32_t pf[4][4];
        #pragma unroll
        for (int nt = 0; nt < 8; nt++) {
            uint32_t e01 = ex2h2(h2pack(accS[nt][0] * LOG2E, accS[nt][1] * LOG2E));
            uint32_t e23 = ex2h2(h2pack(accS[nt][2] * LOG2E, accS[nt][3] * LOG2E));
            pf[nt >> 1][(nt & 1) * 2 + 0] = e01;
            pf[nt >> 1][(nt & 1) * 2 + 1] = e23;
        }

        // ---- row sums via ones-MMA ----
        #pragma unroll
        for (int ks = 0; ks < 4; ks++)
            mma_f16(accL, pf[ks], ones2);

        // ---- O += P V ----
        const uint32_t vbase = smb + (uint32_t)((A_OFF_V + s * A_VSTG) * 2);
        #pragma unroll
        for (int ks = 0; ks < 4; ks++) {
            const uint32_t rowaddr = vbase + (uint32_t)(((16 * ks + lm_key) * HST) * 2);
            #pragma unroll
            for (int pdp = 0; pdp < 4; pdp++) {
                uint32_t t0, t1, t2, t3;
                LDSM_X4_T(t0, t1, t2, t3,
                          rowaddr + (uint32_t)((16 * pdp + lm_d8) * 2));
                uint32_t b01[2] = { t0, t1 };
                uint32_t b23[2] = { t2, t3 };
                mma_f16(accO[2 * pdp],     pf[ks], b01);
                mma_f16(accO[2 * pdp + 1], pf[ks], b23);
            }
        }
    }

    // ---- epilogue: normalize by exact fp32 row sums, store y (fp16) ----
    const float inv0 = 1.f / accL[0], inv1 = 1.f / accL[2];
    __half* yp = g_yh + ((size_t)b * T_ + qbase + w * 16) * DM + h * DH;
    #pragma unroll
    for (int nt = 0; nt < 8; nt++) {
        const int c = 8 * nt + 2 * tig;
        *(__half2*)(yp + (size_t)g * DM + c) =
            __floats2half2_rn(accO[nt][0] * inv0, accO[nt][1] * inv0);
        *(__half2*)(yp + (size_t)(g + 8) * DM + c) =
            __floats2half2_rn(accO[nt][2] * inv1, accO[nt][3] * inv1);
    }
}

// ---------------------------------------------------------------------------
extern "C" void kernel_launch(void* const* d_in, const int* in_sizes, int n_in,
                              void* d_out, int out_size) {
    const float* x     = (const float*)d_in[0];   // [B,T,1024]
    const float* w_qkv = (const float*)d_in[1];   // [3072,1024]
    const float* w_out = (const float*)d_in[2];   // [1024,1024]
    float* out = (float*)d_out;                   // [B,T,1024]

    __half *qkv_p, *y_p, *xh_p, *wqh_p, *woh_p;
    cudaGetSymbolAddress((void**)&qkv_p, g_qkvh);
    cudaGetSymbolAddress((void**)&y_p,   g_yh);
    cudaGetSymbolAddress((void**)&xh_p,  g_xh);
    cudaGetSymbolAddress((void**)&wqh_p, g_wqh);
    cudaGetSymbolAddress((void**)&woh_p, g_woh);

    cudaFuncSetAttribute(gemm_h, cudaFuncAttributeMaxDynamicSharedMemorySize,
                         GEMM_SMEM);
    cudaFuncSetAttribute(attn_h, cudaFuncAttributeMaxDynamicSharedMemorySize,
                         ATT_SMEM);

    // 0) round all inputs to fp16 (single fused launch)
    {
        int n4 = N4X + N4Q + N4O;
        round_all<<<(n4 + 255) / 256, 256>>>(x, w_qkv, w_out, xh_p, wqh_p, woh_p);
    }

    // 1) qkv = x @ w_qkv^T  (fp16 in, fp16 out)
    {
        dim3 grid(E3 / 128, MTOT / 128);
        gemm_h<<<grid, 256, GEMM_SMEM>>>(xh_p, wqh_p, qkv_p, E3, DM, 1);
    }

    // 2) flash attention (fp16 tensor core, max-free softmax) -> g_yh
    {
        dim3 grid(T_ / 128, H_, B_);
        attn_h<<<grid, 256, ATT_SMEM>>>();
    }

    // 3) out = y @ w_out^T  (fp16 in, fp32 out)
    {
        dim3 grid(DM / 128, MTOT / 128);
        gemm_h<<<grid, 256, GEMM_SMEM>>>(y_p, woh_p, out, DM, DM, 0);
    }
}